// round 1
// baseline (speedup 1.0000x reference)
#include <cuda_runtime.h>
#include <cstdint>

#define CASCADES 3
#define GS3 16777216              // 256^3 cells per cascade
#define NCOORD 4194304            // GS3 / 4 coords per cascade
#define TOTAL_CELLS (CASCADES * GS3)          // 50331648
#define BITS_BYTES  (TOTAL_CELLS / 8)         // 6291456

// Scratch: per-cell winner = (coord_index + 1), 0 = no write.
// __device__ global (no allocation allowed in kernel_launch).
__device__ unsigned g_win[TOTAL_CELLS];

__device__ __forceinline__ unsigned p1b2(unsigned x) {
    x &= 0x3FFu;
    x = (x | (x << 16)) & 0x030000FFu;
    x = (x | (x << 8))  & 0x0300F00Fu;
    x = (x | (x << 4))  & 0x030C30C3u;
    x = (x | (x << 2))  & 0x09249249u;
    return x;
}

__global__ void zero_k(uint4* __restrict__ p, int n4) {
    int i = blockIdx.x * blockDim.x + threadIdx.x;
    if (i < n4) p[i] = make_uint4(0u, 0u, 0u, 0u);
}

__global__ void scatter_k(const int* __restrict__ coords,
                          unsigned* __restrict__ win, int n) {
    int i = blockIdx.x * blockDim.x + threadIdx.x;
    if (i < n) {
        unsigned x = (unsigned)coords[3 * i + 0];
        unsigned y = (unsigned)coords[3 * i + 1];
        unsigned z = (unsigned)coords[3 * i + 2];
        unsigned m = p1b2(x) | (p1b2(y) << 1) | (p1b2(z) << 2);
        // last-write-wins: highest coord index wins (matches sequential scatter)
        atomicMax(win + m, (unsigned)(i + 1));
    }
}

template <int FLOATBITS>
__global__ void combine_k(const float* __restrict__ density,
                          const float* __restrict__ sigmas,
                          const unsigned* __restrict__ win,
                          float* __restrict__ out_grid,
                          uint8_t* __restrict__ out_bits_u8,
                          float* __restrict__ out_bits_f) {
    int t = blockIdx.x * blockDim.x + threadIdx.x;   // one byte (8 cells) per thread
    if (t >= GS3 / 8) return;

    uint4 w0 = ((const uint4*)win)[2 * t + 0];
    uint4 w1 = ((const uint4*)win)[2 * t + 1];
    float4 d0 = ((const float4*)density)[2 * t + 0];
    float4 d1 = ((const float4*)density)[2 * t + 1];

    unsigned ws[8] = {w0.x, w0.y, w0.z, w0.w, w1.x, w1.y, w1.z, w1.w};
    float    dv[8] = {d0.x, d0.y, d0.z, d0.w, d1.x, d1.y, d1.z, d1.w};
    float    v[8];
    unsigned byte = 0u;

#pragma unroll
    for (int b = 0; b < 8; b++) {
        float val = dv[b];
        unsigned w = ws[b];
        if (w) {
            float s = __ldg(sigmas + (w - 1u));   // DENSITY_SCALE == 1.0
            if (val >= 0.0f && s >= 0.0f)         // valid = old>=0 && new>=0
                val = fmaxf(0.95f * val, s);      // DECAY = 0.95
        }
        v[b] = val;
        if (val > 0.01f) byte |= (1u << b);       // DENSITY_THRESHOLD = 0.01
    }

    ((float4*)out_grid)[2 * t + 0] = make_float4(v[0], v[1], v[2], v[3]);
    ((float4*)out_grid)[2 * t + 1] = make_float4(v[4], v[5], v[6], v[7]);

    if (FLOATBITS) {
        out_bits_f[t] = (float)byte;
    } else {
        out_bits_u8[t] = (uint8_t)byte;
    }
}

extern "C" void kernel_launch(void* const* d_in, const int* in_sizes, int n_in,
                              void* d_out, int out_size) {
    const float* density = (const float*)d_in[0];   // [3, 256^3] f32
    const float* sigmas  = (const float*)d_in[1];   // [3, NCOORD] f32
    const int*   coords  = (const int*)d_in[2];     // [3, NCOORD, 3] i32

    unsigned* win = nullptr;
    cudaGetSymbolAddress((void**)&win, g_win);

    // Output layout: reference returns (new_grid f32, bitfield u8).
    //  - If harness dtype is float32: out_size == TOTAL_CELLS + BITS_BYTES elements.
    //  - If harness dtype is uint8:  out_size == TOTAL_CELLS*4 + BITS_BYTES bytes.
    const long long f32_elems = (long long)TOTAL_CELLS + (long long)BITS_BYTES;
    bool floatbits = ((long long)out_size == f32_elems);

    float*   out_grid = (float*)d_out;
    uint8_t* bits_u8  = (uint8_t*)d_out + (size_t)TOTAL_CELLS * 4;
    float*   bits_f   = (float*)d_out + (size_t)TOTAL_CELLS;

    const int ZB = (GS3 / 4) / 256;      // zero kernel blocks (uint4 granularity)
    const int SB = NCOORD / 256;         // scatter blocks
    const int CB = (GS3 / 8) / 256;      // combine blocks

    // Per-cascade pipeline so the 64MB winner array + 16MB sigma table stay
    // hot in the 126MB L2 between scatter and combine.
    for (int c = 0; c < CASCADES; c++) {
        unsigned*    winc = win + (size_t)c * GS3;
        const float* denc = density + (size_t)c * GS3;
        const float* sigc = sigmas + (size_t)c * NCOORD;
        const int*   crdc = coords + (size_t)c * NCOORD * 3;

        zero_k<<<ZB, 256>>>((uint4*)winc, GS3 / 4);
        scatter_k<<<SB, 256>>>(crdc, winc, NCOORD);
        if (floatbits) {
            combine_k<1><<<CB, 256>>>(denc, sigc, winc,
                                      out_grid + (size_t)c * GS3,
                                      nullptr,
                                      bits_f + (size_t)c * (GS3 / 8));
        } else {
            combine_k<0><<<CB, 256>>>(denc, sigc, winc,
                                      out_grid + (size_t)c * GS3,
                                      bits_u8 + (size_t)c * (GS3 / 8),
                                      nullptr);
        }
    }
}